// round 14
// baseline (speedup 1.0000x reference)
#include <cuda_runtime.h>

// Problem constants (fixed by reference: B=32, C=2, H=512, W=512, L=3)
#define BB   32
#define HH   512
#define WW   512
#define LVAL 3.0f
#define ROWS_PER_BLOCK 16
#define NBLOCKS (HH / ROWS_PER_BLOCK * BB)

// Persistent scratch (allocation-free). Zero-initialized at module load;
// the last block resets it after each run so graph replays stay correct.
__device__ double g_part[BB];
__device__ unsigned int g_count = 0;

__device__ __forceinline__ void cp_async16(void* smem_dst, const void* gsrc) {
    unsigned sa = (unsigned)__cvta_generic_to_shared(smem_dst);
    asm volatile("cp.async.cg.shared.global [%0], [%1], 16;" :: "r"(sa), "l"(gsrc));
}
#define CP_COMMIT() asm volatile("cp.async.commit_group;" ::: "memory")
#define CP_WAIT1()  asm volatile("cp.async.wait_group 1;" ::: "memory")

// Compile-time select of 5 consecutive floats at phase O from two aligned
// float4s. Pure register renaming — zero instructions at runtime.
template <int O>
__device__ __forceinline__ void sel5_t(const float4 A, const float4 B, float v[5]) {
    if constexpr (O == 0) { v[0]=A.x; v[1]=A.y; v[2]=A.z; v[3]=A.w; v[4]=B.x; }
    else if constexpr (O == 1) { v[0]=A.y; v[1]=A.z; v[2]=A.w; v[3]=B.x; v[4]=B.y; }
    else if constexpr (O == 2) { v[0]=A.z; v[1]=A.w; v[2]=B.x; v[3]=B.y; v[4]=B.z; }
    else { v[0]=A.w; v[1]=B.x; v[2]=B.y; v[3]=B.z; v[4]=B.w; }
}

// Stage one 2-row (x 2 channel) group of Flow rows into the smem ring.
// 4 instances x 2KB = 8KB = 512 x 16B chunks; 256 threads x 2 chunks.
__device__ __forceinline__ void stage_rows2(
    float (*sf)[8][WW], const float* __restrict__ fbase,
    int tid, int base, int k0)
{
    #pragma unroll
    for (int q = 0; q < 2; q++) {
        const int c    = tid + 256 * q;
        const int inst = c >> 7;              // 0..3
        const int col  = (c & 127) << 2;      // float index, 16B chunks
        const int ch   = inst & 1;
        const int k    = k0 + (inst >> 1);
        if (k <= ROWS_PER_BLOCK) {            // rows 0..16 needed
            const int gr = min(base + k, HH - 1);
            cp_async16(&sf[ch][k & 7][col],
                       fbase + ((size_t)ch * HH + gr) * WW + col);
        }
    }
}

// Stage the 3-row prologue group (6 instances = 768 chunks; 3 per thread).
__device__ __forceinline__ void stage_rows3(
    float (*sf)[8][WW], const float* __restrict__ fbase,
    int tid, int base)
{
    #pragma unroll
    for (int q = 0; q < 3; q++) {
        const int c    = tid + 256 * q;
        const int inst = c >> 7;              // 0..5
        const int col  = (c & 127) << 2;
        const int ch   = inst & 1;
        const int k    = inst >> 1;           // 0..2
        const int gr   = min(base + k, HH - 1);
        cp_async16(&sf[ch][k & 7][col],
                   fbase + ((size_t)ch * HH + gr) * WW + col);
    }
}

// Pipelined row loop, specialized on the (block-uniform) window phase O.
template <int O>
__device__ __forceinline__ float run_rows(
    float (*sf)[8][WW],
    const float* __restrict__ f0, const float* __restrict__ f1,
    const float* __restrict__ m0base,
    int tid, int s, int y0, int hp, int ix1, int a, int x0,
    bool chunk_live, bool fast, int base,
    float w11, float w12, float w21, float w22,
    float b0, float b1, const float wv[4])
{
    float sum = 0.f;

    // Prologue: rows 0-2 (group A), rows 3-4 (group B); PM for it=0.
    stage_rows3(sf, f0, tid, base);
    CP_COMMIT();
    stage_rows2(sf, f0, tid, base, 3);
    CP_COMMIT();

    const int ybase = y0 + s;
    float4 P0c = *(const float4*)(f0 + (size_t)ybase * WW + x0);
    float4 P1c = *(const float4*)(f1 + (size_t)ybase * WW + x0);
    float4 M0c = __ldcs((const float4*)(m0base + (size_t)ybase * WW + x0));
    float4 M1c = __ldcs((const float4*)(m0base + ((size_t)HH + ybase) * WW + x0));

    CP_WAIT1();            // group A (rows 0-2) complete
    __syncthreads();       // visible block-wide

    #pragma unroll 2
    for (int it = 0; it < ROWS_PER_BLOCK / 2; it++) {
        const int y = ybase + 2 * it;

        // Register-prefetch PM for next iteration (always in-bounds: y <= y0+15 <= 511).
        float4 P0n, P1n, M0n, M1n;
        if (it < ROWS_PER_BLOCK / 2 - 1) {
            const int yn = y + 2;
            P0n = *(const float4*)(f0 + (size_t)yn * WW + x0);
            P1n = *(const float4*)(f1 + (size_t)yn * WW + x0);
            M0n = __ldcs((const float4*)(m0base + (size_t)yn * WW + x0));
            M1n = __ldcs((const float4*)(m0base + ((size_t)HH + yn) * WW + x0));
        }

        // Compute (guarded; loop structure stays uniform for the barriers).
        if (chunk_live && y < hp) {
            const int l  = s + 2 * it;        // local shifted-row index
            const int sl1 = l & 7;
            const int sl2 = (l + 1) & 7;

            const float P0a[4] = {P0c.x, P0c.y, P0c.z, P0c.w};
            const float P1a[4] = {P1c.x, P1c.y, P1c.z, P1c.w};
            const float M0a[4] = {M0c.x, M0c.y, M0c.z, M0c.w};
            const float M1a[4] = {M1c.x, M1c.y, M1c.z, M1c.w};

            if (fast) {
                const float4 A00 = *(const float4*)&sf[0][sl1][a];
                const float4 B00 = *(const float4*)&sf[0][sl1][a + 4];
                const float4 A01 = *(const float4*)&sf[0][sl2][a];
                const float4 B01 = *(const float4*)&sf[0][sl2][a + 4];
                const float4 A10 = *(const float4*)&sf[1][sl1][a];
                const float4 B10 = *(const float4*)&sf[1][sl1][a + 4];
                const float4 A11 = *(const float4*)&sf[1][sl2][a];
                const float4 B11 = *(const float4*)&sf[1][sl2][a + 4];

                float v00[5], v01[5], v10[5], v11[5];
                sel5_t<O>(A00, B00, v00);
                sel5_t<O>(A01, B01, v01);
                sel5_t<O>(A10, B10, v10);
                sel5_t<O>(A11, B11, v11);

                #pragma unroll
                for (int i = 0; i < 4; i++) {
                    const float ph0 = w11 * v00[i] + w12 * v00[i + 1]
                                    + w21 * v01[i] + w22 * v01[i + 1];
                    const float ph1 = w11 * v10[i] + w12 * v10[i + 1]
                                    + w21 * v11[i] + w22 * v11[i + 1];
                    const float d0 = P0a[i] - ph0;
                    const float d1 = P1a[i] - ph1;
                    const float sq = d1 * b0 - d0 * b1;
                    sum += (M0a[i] + M1a[i]) * wv[i] * (sq * sq);
                }
            } else {
                // Edge chunk: scalar LDS, only valid pixels (c in [0, W-2]).
                #pragma unroll
                for (int i = 0; i < 4; i++) {
                    if (wv[i] == 0.f) continue;
                    const int c = x0 + i + ix1;
                    const float ph0 = w11 * sf[0][sl1][c] + w12 * sf[0][sl1][c + 1]
                                    + w21 * sf[0][sl2][c] + w22 * sf[0][sl2][c + 1];
                    const float ph1 = w11 * sf[1][sl1][c] + w12 * sf[1][sl1][c + 1]
                                    + w21 * sf[1][sl2][c] + w22 * sf[1][sl2][c + 1];
                    const float d0 = P0a[i] - ph0;
                    const float d1 = P1a[i] - ph1;
                    const float sq = d1 * b0 - d0 * b1;
                    sum += (M0a[i] + M1a[i]) * (sq * sq);
                }
            }
        }

        __syncthreads();                       // all reads of recycled slots done
        stage_rows2(sf, f0, tid, base, 2 * it + 5);
        CP_COMMIT();
        CP_WAIT1();                            // rows 2it+3, 2it+4 complete
        __syncthreads();                       // visible for it+1

        P0c = P0n; P1c = P1n; M0c = M0n; M1c = M1n;
    }
    return sum;
}

// Grid: (H/16, B). Block: 256 = 2 subrows x 128 chunk-threads.
__global__ __launch_bounds__(256, 4) void symloss_kernel(
    const float* __restrict__ Flow,   // (B,2,H,W)
    const float* __restrict__ Asym,   // (B,2)
    const float* __restrict__ Bsym,   // (B,2)
    const float* __restrict__ Mask,   // (B,2,H,W)
    float* __restrict__ out)
{
    __shared__ float s_flow[2][8][WW];         // 32KB ring: 8 rows x 2 channels

    const int tid = threadIdx.x;
    const int b  = blockIdx.y;
    const int s  = tid >> 7;
    const int j  = tid & 127;
    const int x0 = j << 2;
    const int y0 = blockIdx.x * ROWS_PER_BLOCK;

    const float a0 = Asym[2 * b];
    const float a1 = Asym[2 * b + 1];
    const float b0 = Bsym[2 * b];
    const float b1 = Bsym[2 * b + 1];

    const float dxs = -LVAL * a0;
    const float dys = fabsf(LVAL * a1);
    const float dy1 = floorf(dys);
    const float dx1 = floorf(dxs);
    const float fy  = dys - dy1;
    const float fx  = dxs - dx1;
    const int iy1 = (int)dy1;          // >= 0
    const int ix1 = (int)dx1;          // may be negative

    const int hp   = HH - 1 - iy1;
    const int x_lo = max(0, -ix1);
    const int x_hi = min(WW, WW - 1 - ix1);
    const int base = min(y0 + iy1, HH - 1);   // first shifted row staged

    const float w11 = (1.f - fx) * (1.f - fy);
    const float w12 = fx * (1.f - fy);
    const float w21 = (1.f - fx) * fy;
    const float w22 = fx * fy;

    // Iteration-invariant chunk geometry.
    const int c0 = x0 + ix1;
    const int o  = c0 & 3;             // block-uniform (x0 % 4 == 0, ix1 sample-constant)
    const int a  = c0 - o;             // 4-aligned
    const bool chunk_live = (x_hi > x_lo) && (x0 + 3 >= x_lo) && (x0 < x_hi);
    const bool fast = chunk_live && (a >= 0) && (a + 8 <= WW);

    float wv[4];                       // 0/1 per-pixel valid weights (iteration-invariant)
    #pragma unroll
    for (int i = 0; i < 4; i++) {
        const int x = x0 + i;
        wv[i] = ((x >= x_lo) && (x < x_hi)) ? 1.f : 0.f;
    }

    const float* f0 = Flow + ((size_t)(2 * b) * HH) * WW;
    const float* f1 = f0 + (size_t)HH * WW;
    const float* m0base = Mask + ((size_t)(2 * b) * HH) * WW;

    // One uniform dispatch on the block-constant phase; sel5 becomes free.
    float sum;
    switch (o) {
    case 0:  sum = run_rows<0>(s_flow, f0, f1, m0base, tid, s, y0, hp, ix1, a, x0,
                               chunk_live, fast, base, w11, w12, w21, w22, b0, b1, wv); break;
    case 1:  sum = run_rows<1>(s_flow, f0, f1, m0base, tid, s, y0, hp, ix1, a, x0,
                               chunk_live, fast, base, w11, w12, w21, w22, b0, b1, wv); break;
    case 2:  sum = run_rows<2>(s_flow, f0, f1, m0base, tid, s, y0, hp, ix1, a, x0,
                               chunk_live, fast, base, w11, w12, w21, w22, b0, b1, wv); break;
    default: sum = run_rows<3>(s_flow, f0, f1, m0base, tid, s, y0, hp, ix1, a, x0,
                               chunk_live, fast, base, w11, w12, w21, w22, b0, b1, wv); break;
    }

    // Block reduction: warp shuffle + shared.
    __shared__ float warp_sums[8];
    __shared__ bool  is_last;
    #pragma unroll
    for (int off = 16; off > 0; off >>= 1)
        sum += __shfl_down_sync(0xffffffffu, sum, off);

    const int lane = tid & 31;
    const int wid  = tid >> 5;
    if (lane == 0) warp_sums[wid] = sum;
    __syncthreads();

    if (tid == 0) {
        float total = 0.f;
        #pragma unroll
        for (int wv2 = 0; wv2 < 8; wv2++) total += warp_sums[wv2];
        if (total != 0.f) {
            const float denom = 2.f * (float)max(hp, 1) * (float)max(x_hi - x_lo, 1);
            atomicAdd(&g_part[b], (double)(total / denom) * (1.0 / (double)BB));
        }
        __threadfence();
        const unsigned int prev = atomicAdd(&g_count, 1u);
        is_last = (prev == (unsigned int)(NBLOCKS - 1));
    }
    __syncthreads();

    // Last block finalizes and resets state for the next graph replay.
    if (is_last && tid == 0) {
        double acc = 0.0;
        #pragma unroll
        for (int i = 0; i < BB; i++) {
            acc += g_part[i];
            g_part[i] = 0.0;
        }
        out[0] = (float)acc;
        __threadfence();
        g_count = 0;
    }
}

extern "C" void kernel_launch(void* const* d_in, const int* in_sizes, int n_in,
                              void* d_out, int out_size) {
    const float* Flow = (const float*)d_in[0];
    const float* Asym = (const float*)d_in[1];
    const float* Bsym = (const float*)d_in[2];
    const float* Mask = (const float*)d_in[3];
    float* out = (float*)d_out;

    dim3 grid(HH / ROWS_PER_BLOCK, BB);
    symloss_kernel<<<grid, 256>>>(Flow, Asym, Bsym, Mask, out);
}

// round 15
// speedup vs baseline: 1.1240x; 1.1240x over previous
#include <cuda_runtime.h>

// Problem constants (fixed by reference: B=32, C=2, H=512, W=512, L=3)
#define BB   32
#define HH   512
#define WW   512
#define LVAL 3.0f
#define ROWS_PER_BLOCK 32
#define NBLOCKS (HH / ROWS_PER_BLOCK * BB)

// Persistent scratch (allocation-free). Zero-initialized at module load;
// the last block resets it after each run so graph replays stay correct.
__device__ double g_part[BB];
__device__ unsigned int g_count = 0;

// Compile-time select of 5 consecutive floats at phase O from two aligned
// float4s. Pure register renaming — zero instructions at runtime.
template <int O>
__device__ __forceinline__ void sel5_t(const float4 A, const float4 B, float v[5]) {
    if constexpr (O == 0) { v[0]=A.x; v[1]=A.y; v[2]=A.z; v[3]=A.w; v[4]=B.x; }
    else if constexpr (O == 1) { v[0]=A.y; v[1]=A.z; v[2]=A.w; v[3]=B.x; v[4]=B.y; }
    else if constexpr (O == 2) { v[0]=A.z; v[1]=A.w; v[2]=B.x; v[3]=B.y; v[4]=B.z; }
    else { v[0]=A.w; v[1]=B.x; v[2]=B.y; v[3]=B.z; v[4]=B.w; }
}

// Row loop specialized on the (block-uniform) window phase O.
template <int O>
__device__ __forceinline__ float run_rows(
    const float* __restrict__ f0, const float* __restrict__ f1,
    const float* __restrict__ m0base,
    int ybase, int hp, int iy1, int ix1, int a, int x0,
    bool chunk_live, bool fast,
    float w11, float w12, float w21, float w22,
    float b0, float b1, const float wv[4])
{
    float sum = 0.f;

    #pragma unroll 2
    for (int it = 0; it < ROWS_PER_BLOCK / 2; it++) {
        const int y = ybase + 2 * it;
        if (!chunk_live || y >= hp) continue;

        const int r1 = y + iy1;        // <= H-2 for valid rows
        const float* m0 = m0base + (size_t)y * WW;
        const float* m1 = m0 + (size_t)HH * WW;

        const float4 M0 = __ldcs((const float4*)(m0 + x0));   // streaming, evict-first
        const float4 M1 = __ldcs((const float4*)(m1 + x0));   // streaming, evict-first
        const float4 P0 = *(const float4*)(f0 + (size_t)y * WW + x0);
        const float4 P1 = *(const float4*)(f1 + (size_t)y * WW + x0);
        const float M0a[4] = {M0.x, M0.y, M0.z, M0.w};
        const float M1a[4] = {M1.x, M1.y, M1.z, M1.w};
        const float P0a[4] = {P0.x, P0.y, P0.z, P0.w};
        const float P1a[4] = {P1.x, P1.y, P1.z, P1.w};

        if (fast) {
            const float* p0r1 = f0 + (size_t)r1 * WW + a;
            const float* p0r2 = p0r1 + WW;
            const float* p1r1 = f1 + (size_t)r1 * WW + a;
            const float* p1r2 = p1r1 + WW;
            const float4 A00 = *(const float4*)(p0r1);
            const float4 B00 = *(const float4*)(p0r1 + 4);
            const float4 A01 = *(const float4*)(p0r2);
            const float4 B01 = *(const float4*)(p0r2 + 4);
            const float4 A10 = *(const float4*)(p1r1);
            const float4 B10 = *(const float4*)(p1r1 + 4);
            const float4 A11 = *(const float4*)(p1r2);
            const float4 B11 = *(const float4*)(p1r2 + 4);

            float v00[5], v01[5], v10[5], v11[5];
            sel5_t<O>(A00, B00, v00);   // ch0, row r1: flow0[r1][c0 .. c0+4]
            sel5_t<O>(A01, B01, v01);   // ch0, row r2
            sel5_t<O>(A10, B10, v10);   // ch1, row r1
            sel5_t<O>(A11, B11, v11);   // ch1, row r2

            #pragma unroll
            for (int i = 0; i < 4; i++) {
                const float ph0 = w11 * v00[i] + w12 * v00[i + 1]
                                + w21 * v01[i] + w22 * v01[i + 1];
                const float ph1 = w11 * v10[i] + w12 * v10[i + 1]
                                + w21 * v11[i] + w22 * v11[i + 1];
                const float d0 = P0a[i] - ph0;
                const float d1 = P1a[i] - ph1;
                const float sq = d1 * b0 - d0 * b1;
                sum += (M0a[i] + M1a[i]) * wv[i] * (sq * sq);
            }
        } else {
            // Edge chunk: scalar loads, only for valid pixels (c in [0, W-2]).
            const float* p0r1 = f0 + (size_t)r1 * WW;
            const float* p0r2 = p0r1 + WW;
            const float* p1r1 = f1 + (size_t)r1 * WW;
            const float* p1r2 = p1r1 + WW;
            #pragma unroll
            for (int i = 0; i < 4; i++) {
                if (wv[i] == 0.f) continue;
                const int c = x0 + i + ix1;
                const float ph0 = w11 * p0r1[c] + w12 * p0r1[c + 1]
                                + w21 * p0r2[c] + w22 * p0r2[c + 1];
                const float ph1 = w11 * p1r1[c] + w12 * p1r1[c + 1]
                                + w21 * p1r2[c] + w22 * p1r2[c + 1];
                const float d0 = P0a[i] - ph0;
                const float d1 = P1a[i] - ph1;
                const float sq = d1 * b0 - d0 * b1;
                sum += (M0a[i] + M1a[i]) * (sq * sq);
            }
        }
    }
    return sum;
}

// Grid: (H/32, B) = 512 blocks — a single wave at 4 blocks/SM on 148 SMs.
// Block: 256 = 2 subrows x 128 chunk-threads.
// Thread (s, j) handles pixels x in [4j, 4j+4) of rows y = 32*bx + s + 2*it, it=0..15.
__global__ __launch_bounds__(256, 4) void symloss_kernel(
    const float* __restrict__ Flow,   // (B,2,H,W)
    const float* __restrict__ Asym,   // (B,2)
    const float* __restrict__ Bsym,   // (B,2)
    const float* __restrict__ Mask,   // (B,2,H,W)
    float* __restrict__ out)
{
    const int b  = blockIdx.y;
    const int s  = threadIdx.x >> 7;
    const int j  = threadIdx.x & 127;
    const int x0 = j << 2;
    const int ybase = blockIdx.x * ROWS_PER_BLOCK + s;

    const float a0 = Asym[2 * b];
    const float a1 = Asym[2 * b + 1];
    const float b0 = Bsym[2 * b];
    const float b1 = Bsym[2 * b + 1];

    const float dxs = -LVAL * a0;
    const float dys = fabsf(LVAL * a1);
    const float dy1 = floorf(dys);
    const float dx1 = floorf(dxs);
    const float fy  = dys - dy1;
    const float fx  = dxs - dx1;
    const int iy1 = (int)dy1;          // >= 0
    const int ix1 = (int)dx1;          // may be negative

    const int hp   = HH - 1 - iy1;
    const int x_lo = max(0, -ix1);
    const int x_hi = min(WW, WW - 1 - ix1);

    const float w11 = (1.f - fx) * (1.f - fy);
    const float w12 = fx * (1.f - fy);
    const float w21 = (1.f - fx) * fy;
    const float w22 = fx * fy;

    // Iteration-invariant chunk geometry.
    const int c0 = x0 + ix1;
    const int o  = c0 & 3;             // block-uniform (x0 % 4 == 0, ix1 sample-constant)
    const int a  = c0 - o;             // 4-aligned
    const bool chunk_live = (x_hi > x_lo) && (x0 + 3 >= x_lo) && (x0 < x_hi);
    const bool fast = chunk_live && (a >= 0) && (a + 8 <= WW);

    float wv[4];                       // 0/1 per-pixel valid weights (iteration-invariant)
    #pragma unroll
    for (int i = 0; i < 4; i++) {
        const int x = x0 + i;
        wv[i] = ((x >= x_lo) && (x < x_hi)) ? 1.f : 0.f;
    }

    const float* f0 = Flow + ((size_t)(2 * b) * HH) * WW;
    const float* f1 = f0 + (size_t)HH * WW;
    const float* m0base = Mask + ((size_t)(2 * b) * HH) * WW;

    // One uniform dispatch on the block-constant phase; sel5 becomes free.
    float sum;
    switch (o) {
    case 0:  sum = run_rows<0>(f0, f1, m0base, ybase, hp, iy1, ix1, a, x0,
                               chunk_live, fast, w11, w12, w21, w22, b0, b1, wv); break;
    case 1:  sum = run_rows<1>(f0, f1, m0base, ybase, hp, iy1, ix1, a, x0,
                               chunk_live, fast, w11, w12, w21, w22, b0, b1, wv); break;
    case 2:  sum = run_rows<2>(f0, f1, m0base, ybase, hp, iy1, ix1, a, x0,
                               chunk_live, fast, w11, w12, w21, w22, b0, b1, wv); break;
    default: sum = run_rows<3>(f0, f1, m0base, ybase, hp, iy1, ix1, a, x0,
                               chunk_live, fast, w11, w12, w21, w22, b0, b1, wv); break;
    }

    // Block reduction: warp shuffle + shared.
    __shared__ float warp_sums[8];
    __shared__ bool  is_last;
    #pragma unroll
    for (int off = 16; off > 0; off >>= 1)
        sum += __shfl_down_sync(0xffffffffu, sum, off);

    const int lane = threadIdx.x & 31;
    const int wid  = threadIdx.x >> 5;
    if (lane == 0) warp_sums[wid] = sum;
    __syncthreads();

    if (threadIdx.x == 0) {
        float total = 0.f;
        #pragma unroll
        for (int wv2 = 0; wv2 < 8; wv2++) total += warp_sums[wv2];
        if (total != 0.f) {
            const float denom = 2.f * (float)max(hp, 1) * (float)max(x_hi - x_lo, 1);
            atomicAdd(&g_part[b], (double)(total / denom) * (1.0 / (double)BB));
        }
        __threadfence();
        const unsigned int prev = atomicAdd(&g_count, 1u);
        is_last = (prev == (unsigned int)(NBLOCKS - 1));
    }
    __syncthreads();

    // Last block finalizes and resets state for the next graph replay.
    if (is_last && threadIdx.x == 0) {
        double acc = 0.0;
        #pragma unroll
        for (int i = 0; i < BB; i++) {
            acc += g_part[i];
            g_part[i] = 0.0;
        }
        out[0] = (float)acc;
        __threadfence();
        g_count = 0;
    }
}

extern "C" void kernel_launch(void* const* d_in, const int* in_sizes, int n_in,
                              void* d_out, int out_size) {
    const float* Flow = (const float*)d_in[0];
    const float* Asym = (const float*)d_in[1];
    const float* Bsym = (const float*)d_in[2];
    const float* Mask = (const float*)d_in[3];
    float* out = (float*)d_out;

    dim3 grid(HH / ROWS_PER_BLOCK, BB);
    symloss_kernel<<<grid, 256>>>(Flow, Asym, Bsym, Mask, out);
}